// round 17
// baseline (speedup 1.0000x reference)
#include <cuda_runtime.h>
#include <cuda_fp16.h>
#include <math.h>

#define BATCH 32
#define H 512
#define W 512
#define HW (H*W)
#define NTOT (BATCH*HW)
#define KK_INV (1.0f/961.0f)

#define ROWS_PB 16
#define NTHR 128
#define NBLKY (H / ROWS_PB)                 // 32
#define NBLK (BATCH * NBLKY)                // 1024
#define CHUNKS_PER_IMG NBLKY                // 32

__device__ __half   g_hsum[NTOT];           // fp16 horizontal 31-box sums
__device__ float    g_part[NBLK][4];        // {bce, wsum, inter, union}
__device__ unsigned g_done = 0;

__device__ __forceinline__ float tanh_fast(float x) {
    float r;
    asm("tanh.approx.f32 %0, %1;" : "=f"(r) : "f"(x));
    return r;
}

// ---------------------------------------------------------------------------
// Kernel 1: warp-per-row horizontal 31-box sum -> fp16 gmem.
// Chain-broken: 4 front-batched float4 loads, 4 parallel warp scans,
// gather via per-warp smem prefix scratch. Each row computed exactly once.
// ---------------------------------------------------------------------------
__global__ __launch_bounds__(256) void hpass_kernel(const float* __restrict__ targ) {
    const unsigned FULL = 0xffffffffu;
    const int wslot = threadIdx.x >> 5;
    const int lane  = threadIdx.x & 31;
    const int row   = blockIdx.x * 8 + wslot;          // 0 .. BATCH*H-1

    __shared__ float Psm[8][W];
    float4* P4 = (float4*)Psm[wslot];

    const float4* __restrict__ rowp = (const float4*)(targ + (size_t)row * W);
    uint2* __restrict__ outp = (uint2*)(g_hsum + (size_t)row * W);

    const float4 q0 = rowp[lane];
    const float4 q1 = rowp[32 + lane];
    const float4 q2 = rowp[64 + lane];
    const float4 q3 = rowp[96 + lane];

    const float a1 = q0.x, a2 = a1 + q0.y, a3 = a2 + q0.z, a4 = a3 + q0.w;
    const float b1 = q1.x, b2 = b1 + q1.y, b3 = b2 + q1.z, b4 = b3 + q1.w;
    const float c1 = q2.x, c2 = c1 + q2.y, c3 = c2 + q2.z, c4 = c3 + q2.w;
    const float d1 = q3.x, d2 = d1 + q3.y, d3 = d2 + q3.z, d4 = d3 + q3.w;

    float s0 = a4, s1 = b4, s2 = c4, s3 = d4;
    #pragma unroll
    for (int off = 1; off < 32; off <<= 1) {
        float n0 = __shfl_up_sync(FULL, s0, off);
        float n1 = __shfl_up_sync(FULL, s1, off);
        float n2 = __shfl_up_sync(FULL, s2, off);
        float n3 = __shfl_up_sync(FULL, s3, off);
        if (lane >= off) { s0 += n0; s1 += n1; s2 += n2; s3 += n3; }
    }
    const float T0 = __shfl_sync(FULL, s0, 31);
    const float T1 = __shfl_sync(FULL, s1, 31);
    const float T2 = __shfl_sync(FULL, s2, 31);
    const float T3 = __shfl_sync(FULL, s3, 31);

    const float e0 = s0 - a4;
    const float e1 = T0 + (s1 - b4);
    const float e2 = T0 + T1 + (s2 - c4);
    const float e3 = T0 + T1 + T2 + (s3 - d4);
    const float total = T0 + T1 + T2 + T3;

    P4[lane]      = make_float4(e0 + a1, e0 + a2, e0 + a3, e0 + a4);
    P4[32 + lane] = make_float4(e1 + b1, e1 + b2, e1 + b3, e1 + b4);
    P4[64 + lane] = make_float4(e2 + c1, e2 + c2, e2 + c3, e2 + c4);
    P4[96 + lane] = make_float4(e3 + d1, e3 + d2, e3 + d3, e3 + d4);
    __syncwarp();

    // out[x] = P[min(x+15,511)] - (x>=16 ? P[x-16] : 0), stored as fp16
    #pragma unroll
    for (int c = 0; c < 4; ++c) {
        const int g = c * 32 + lane;
        float4 A;
        if (g < 124) {
            float4 Q1 = P4[g + 3];
            float4 Q2 = P4[g + 4];
            A = make_float4(Q1.w, Q2.x, Q2.y, Q2.z);
        } else {
            A = make_float4(total, total, total, total);
        }
        float4 B = (g >= 4) ? P4[g - 4] : make_float4(0.f, 0.f, 0.f, 0.f);
        __half2 h0 = __floats2half2_rn(A.x - B.x, A.y - B.y);
        __half2 h1 = __floats2half2_rn(A.z - B.z, A.w - B.w);
        uint2 u;
        u.x = *reinterpret_cast<unsigned*>(&h0);
        u.y = *reinterpret_cast<unsigned*>(&h1);
        outp[g] = u;
    }
}

// 2-MUFU loss math: p via tanh.approx, softplus via log of the same tanh.
__device__ __forceinline__ void lane_math(float xv, float tv, float vsum,
                                          float& bce, float& ws, float& it, float& un) {
    const float w  = fmaf(5.0f, fabsf(vsum * KK_INV - tv), 1.0f);
    const float th = tanh_fast(0.5f * xv);
    const float p  = fmaf(0.5f, th, 0.5f);
    const float sp = fmaxf(xv, 0.0f) - __logf(fmaf(0.5f, fabsf(th), 0.5f));
    bce += sp - xv * tv;
    ws  += w;
    it  += p * tv * w;
    un  += (p + tv) * w;
}

__device__ __forceinline__ float2 h2f(unsigned u) {
    return __half22float2(*reinterpret_cast<__half2*>(&u));
}

// ---------------------------------------------------------------------------
// Kernel 2: vertical sliding-window + loss. grid (32, 32), block 128.
// No smem pipeline, no barriers in the main loop. Thread owns 4 columns.
// hsum rows stream from gmem (L2-resident). Last block finalizes.
// ---------------------------------------------------------------------------
__global__ __launch_bounds__(NTHR, 6)
void loss_kernel(const float* __restrict__ pred,
                 const float* __restrict__ targ,
                 float* __restrict__ out) {
    __shared__ float red[4 * NTHR];
    __shared__ unsigned last_flag;

    const int b   = blockIdx.y;
    const int tid = threadIdx.x;
    const int r0  = blockIdx.x * ROWS_PB;

    const float4* __restrict__ tb4 = (const float4*)(targ + (size_t)b * HW);
    const float4* __restrict__ pb4 = (const float4*)(pred + (size_t)b * HW);
    const uint2*  __restrict__ hs2 = (const uint2*)(g_hsum + (size_t)b * HW);

    // Initial vertical window: rows r0-15 .. r0+15 (guarded)
    float vx = 0.f, vy = 0.f, vz = 0.f, vw = 0.f;
    const int ilo = (r0 - 15 < 0) ? 0 : r0 - 15;
    const int ihi = (r0 + 15 >= H) ? H - 1 : r0 + 15;
    for (int row = ilo; row <= ihi; ++row) {
        uint2 u = __ldg(hs2 + row * (W/4) + tid);
        float2 a = h2f(u.x), c = h2f(u.y);
        vx += a.x; vy += a.y; vz += c.x; vw += c.y;
    }

    float bce_a = 0.f, wsum_a = 0.f, inter_a = 0.f, uni_a = 0.f;

    #pragma unroll 4
    for (int r = r0; r < r0 + ROWS_PB; ++r) {
        // issue all loads first (independent)
        const float4 tv = __ldg(tb4 + r * (W/4) + tid);
        const float4 xv = __ldg(pb4 + r * (W/4) + tid);
        const int radd = r + 16, rsub = r - 15;
        uint2 ua = (radd < H)  ? __ldg(hs2 + radd * (W/4) + tid) : make_uint2(0u, 0u);
        uint2 us = (rsub >= 0) ? __ldg(hs2 + rsub * (W/4) + tid) : make_uint2(0u, 0u);

        lane_math(xv.x, tv.x, vx, bce_a, wsum_a, inter_a, uni_a);
        lane_math(xv.y, tv.y, vy, bce_a, wsum_a, inter_a, uni_a);
        lane_math(xv.z, tv.z, vz, bce_a, wsum_a, inter_a, uni_a);
        lane_math(xv.w, tv.w, vw, bce_a, wsum_a, inter_a, uni_a);

        float2 aa = h2f(ua.x), ab = h2f(ua.y);
        float2 sa = h2f(us.x), sb = h2f(us.y);
        vx += aa.x - sa.x;
        vy += aa.y - sa.y;
        vz += ab.x - sb.x;
        vw += ab.y - sb.y;
    }

    // Deterministic block reduction (fixed order)
    red[0 * NTHR + tid] = bce_a;
    red[1 * NTHR + tid] = wsum_a;
    red[2 * NTHR + tid] = inter_a;
    red[3 * NTHR + tid] = uni_a;
    __syncthreads();
    #pragma unroll
    for (int off = NTHR / 2; off > 0; off >>= 1) {
        if (tid < off) {
            red[0 * NTHR + tid] += red[0 * NTHR + tid + off];
            red[1 * NTHR + tid] += red[1 * NTHR + tid + off];
            red[2 * NTHR + tid] += red[2 * NTHR + tid + off];
            red[3 * NTHR + tid] += red[3 * NTHR + tid + off];
        }
        __syncthreads();
    }

    if (tid == 0) {
        const int blin = b * CHUNKS_PER_IMG + blockIdx.x;
        g_part[blin][0] = red[0 * NTHR];
        g_part[blin][1] = red[1 * NTHR];
        g_part[blin][2] = red[2 * NTHR];
        g_part[blin][3] = red[3 * NTHR];
        __threadfence();
        last_flag = (atomicAdd(&g_done, 1u) == NBLK - 1u);
    }
    __syncthreads();
    if (!last_flag) return;

    // ---- Last block: global finalize (fixed-order sums) ----
    __threadfence();
    if (tid == 0) g_done = 0;   // reset for next graph replay

    float acc = 0.0f;
    #pragma unroll
    for (int j = 0; j < NBLK / NTHR; ++j) acc += g_part[tid * (NBLK / NTHR) + j][0];
    red[tid] = acc;
    __syncthreads();
    #pragma unroll
    for (int off = NTHR / 2; off > 0; off >>= 1) {
        if (tid < off) red[tid] += red[tid + off];
        __syncthreads();
    }
    const float bce = red[0] * (1.0f / (float)NTOT);
    __syncthreads();

    if (tid < BATCH) {
        float ws = 0.0f, it = 0.0f, un = 0.0f;
        #pragma unroll
        for (int j = 0; j < CHUNKS_PER_IMG; ++j) {
            const int bl = tid * CHUNKS_PER_IMG + j;
            ws += g_part[bl][1];
            it += g_part[bl][2];
            un += g_part[bl][3];
        }
        const float w_bce = (ws * bce + 1e-8f) / (ws + 1e-8f);
        const float w_iou = 1.0f - (it + 1.0f + 1e-8f) / (un - it + 1.0f + 1e-8f);
        red[NTHR + tid] = w_bce + w_iou;
    }
    __syncthreads();
    if (tid == 0) {
        float a = 0.0f;
        #pragma unroll
        for (int i = 0; i < BATCH; ++i) a += red[NTHR + i];
        out[0] = a * (1.0f / (float)BATCH);
    }
}

// ---------------------------------------------------------------------------
extern "C" void kernel_launch(void* const* d_in, const int* in_sizes, int n_in,
                              void* d_out, int out_size) {
    const float* y_pred   = (const float*)d_in[0];
    const float* y_target = (const float*)d_in[1];
    float* out = (float*)d_out;

    hpass_kernel<<<BATCH * H / 8, 256>>>(y_target);     // 2048 blocks, 8 warps

    dim3 g(NBLKY, BATCH);                               // (32, 32) = 1024 blocks
    loss_kernel<<<g, NTHR>>>(y_pred, y_target, out);
}